// round 10
// baseline (speedup 1.0000x reference)
#include <cuda_runtime.h>
#include <math.h>

#define PI_F 3.14159265358979323846f

// ---------- helpers ----------
__device__ __forceinline__ float2 cmul(float2 a, float2 b){
    return make_float2(a.x*b.x - a.y*b.y, a.x*b.y + a.y*b.x);
}
__device__ __forceinline__ float2 cadd(float2 a, float2 b){ return make_float2(a.x+b.x, a.y+b.y); }
__device__ __forceinline__ float2 expi(float a){ float s,c; __sincosf(a,&s,&c); return make_float2(c,s); }
__device__ __forceinline__ float2 cscale(float2 a, float s){ return make_float2(a.x*s, a.y*s); }
__device__ __forceinline__ float2 shflx(float2 v, int m){
    return make_float2(__shfl_xor_sync(0xffffffffu, v.x, m),
                       __shfl_xor_sync(0xffffffffu, v.y, m));
}
__device__ __forceinline__ float fast_tanh(float x){
    float e = __expf(2.f * x);
    return 1.f - 2.f / (e + 1.f);
}
__device__ __forceinline__ unsigned long long pk2(float x, float y){
    unsigned long long r; asm("mov.b64 %0, {%1,%2};" : "=l"(r) : "f"(x), "f"(y)); return r;
}
__device__ __forceinline__ float2 upk2(unsigned long long a){
    float2 r; asm("mov.b64 {%0,%1}, %2;" : "=f"(r.x), "=f"(r.y) : "l"(a)); return r;
}
__device__ __forceinline__ unsigned long long fma2(unsigned long long a, unsigned long long b,
                                                   unsigned long long c){
    unsigned long long d;
    asm("fma.rn.f32x2 %0, %1, %2, %3;" : "=l"(d) : "l"(a), "l"(b), "l"(c));
    return d;
}

// In-register simulation of the 8-gate initQKV circuit applied to basis state |col>.
// One THREAD holds all 16 amplitudes; compile-time masks; no shfl.
__device__ __forceinline__ void simcol(const float* __restrict__ rot,
                                       const float* __restrict__ crx,
                                       int col, float2* st)
{
    #pragma unroll
    for (int i = 0; i < 16; i++) st[i] = make_float2((i == col) ? 1.f : 0.f, 0.f);
    #pragma unroll
    for (int g = 0; g < 8; g++){
        const int pa_[8] = {0,1,2,3,0,1,2,3};
        const int pb_[8] = {1,2,3,0,3,0,1,2};
        const int ma = 8 >> pa_[g], mb = 8 >> pb_[g];

        float phi = rot[3*g], th = rot[3*g+1], om = rot[3*g+2];
        float c, sn; __sincosf(0.5f*th, &sn, &c);
        float2 u00 = cscale(expi(-0.5f*(phi+om)),  c);
        float2 u01 = cscale(expi( 0.5f*(phi-om)), -sn);
        float2 u10 = cscale(expi(-0.5f*(phi-om)),  sn);
        float2 u11 = cscale(expi( 0.5f*(phi+om)),  c);
        // Rot on wire a
        #pragma unroll
        for (int i = 0; i < 16; i++){
            if (i & ma) continue;
            float2 lo = st[i], hi = st[i|ma];
            st[i]    = cadd(cmul(u00, lo), cmul(u01, hi));
            st[i|ma] = cadd(cmul(u10, lo), cmul(u11, hi));
        }
        // CRX(a -> b)
        float cc, ss; __sincosf(0.5f*crx[g], &ss, &cc);
        #pragma unroll
        for (int i = 0; i < 16; i++){
            if (!(i & ma) || (i & mb)) continue;
            float2 lo = st[i], hi = st[i|mb];
            st[i]    = make_float2(cc*lo.x + ss*hi.y, cc*lo.y - ss*hi.x);
            st[i|mb] = make_float2(cc*hi.x + ss*lo.y, cc*hi.y - ss*lo.x);
        }
        // CNOT(a -> b)
        #pragma unroll
        for (int i = 0; i < 16; i++){
            if (!(i & ma) || (i & mb)) continue;
            float2 tmp = st[i]; st[i] = st[i|mb]; st[i|mb] = tmp;
        }
    }
}

// Single fused kernel. 128 threads = 32 quads; each quad serves TWO samples (ILP-2).
// Preamble: warp-0 threads each build one U column in registers; warp-1 lane 0 builds
// the k state and its <X_w>.
__global__ void __launch_bounds__(128, 3)
qc_kernel(const float* __restrict__ x1, const float* __restrict__ pre_w,
          const float* __restrict__ pre_b,
          const float* __restrict__ q_rot, const float* __restrict__ k_rot,
          const float* __restrict__ v_rot,
          const float* __restrict__ q_crx, const float* __restrict__ k_crx,
          const float* __restrict__ v_crx,
          const float* __restrict__ ln_w, const float* __restrict__ ln_b,
          const float* __restrict__ head_w, const float* __restrict__ head_b,
          float* __restrict__ out, int B)
{
    __shared__ float4 sUq[128];   // 16x16 complex, odd-parity columns pre-rotated by (-i)
    __shared__ float4 sUv[128];
    __shared__ float  sW[384];    // pre_w [4][96]
    __shared__ float  sKx[4];
    __shared__ float  sPB[4];
    __shared__ float  sLnW[8], sLnB[8], sHW[16], sHB[2];

    int t = threadIdx.x;

    // ---- preamble ----
    if (t < 32){
        int col = t & 15;
        const float* rot = (t < 16) ? q_rot : v_rot;
        const float* crx = (t < 16) ? q_crx : v_crx;
        float2 st[16];
        simcol(rot, crx, col, st);
        float2* dst = (float2*)((t < 16) ? sUq : sUv);
        bool oddp = (__popc(col) & 1);
        #pragma unroll
        for (int r = 0; r < 16; r++){
            float2 s = st[r];
            dst[col*16 + r] = oddp ? make_float2(s.y, -s.x) : s;   // pre-rotate by (-i)
        }
    } else if (t < 64){
        if (t == 32){
            float2 st[16];
            simcol(k_rot, k_crx, 0, st);
            #pragma unroll
            for (int w = 0; w < 4; w++){
                int m = 8 >> w;
                float x = 0.f;
                #pragma unroll
                for (int i = 0; i < 16; i++)
                    x += st[i].x*st[i^m].x + st[i].y*st[i^m].y;
                sKx[w] = x;
            }
        }
    } else {
        // warps 2,3 stage the small params
        for (int i = t - 64; i < 384; i += 64) sW[i] = pre_w[i];
        int u = t - 64;
        if (u < 4)              sPB[u]     = pre_b[u];
        if (u >= 4 && u < 12)   sLnW[u-4]  = ln_w[u-4];
        if (u >= 12 && u < 20)  sLnB[u-12] = ln_b[u-12];
        if (u >= 20 && u < 36)  sHW[u-20]  = head_w[u-20];
        if (u >= 36 && u < 38)  sHB[u-36]  = head_b[u-36];
    }
    __syncthreads();

    int q = t >> 2;                      // quad id 0..31
    int l = t & 3;                       // quad lane: rows 4l..4l+3
    int sA = blockIdx.x * 64 + q;
    int sB = sA + 32;
    bool okA = sA < B, okB = sB < B;
    int sAl = okA ? sA : 0;
    int sBl = okB ? sB : 0;

    const float4* sW4 = (const float4*)sW;
    const ulonglong2* Uq64 = (const ulonglong2*)sUq;
    const ulonglong2* Uv64 = (const ulonglong2*)sUv;

    // ---- x = x1[s] @ pre_w.T + pre_b, both samples, shared weights ----
    float a0A=0.f,a1A=0.f,a2A=0.f,a3A=0.f, a0B=0.f,a1B=0.f,a2B=0.f,a3B=0.f;
    {
        const float4* rowA = (const float4*)(x1 + (size_t)sAl * 96) + l * 6;
        const float4* rowB = (const float4*)(x1 + (size_t)sBl * 96) + l * 6;
        #pragma unroll
        for (int k = 0; k < 6; k++){
            float4 vA = rowA[k];
            float4 vB = rowB[k];
            float4 w0 = sW4[      l*6 + k];
            float4 w1 = sW4[ 24 + l*6 + k];
            float4 w2 = sW4[ 48 + l*6 + k];
            float4 w3 = sW4[ 72 + l*6 + k];
            a0A += vA.x*w0.x + vA.y*w0.y + vA.z*w0.z + vA.w*w0.w;
            a1A += vA.x*w1.x + vA.y*w1.y + vA.z*w1.z + vA.w*w1.w;
            a2A += vA.x*w2.x + vA.y*w2.y + vA.z*w2.z + vA.w*w2.w;
            a3A += vA.x*w3.x + vA.y*w3.y + vA.z*w3.z + vA.w*w3.w;
            a0B += vB.x*w0.x + vB.y*w0.y + vB.z*w0.z + vB.w*w0.w;
            a1B += vB.x*w1.x + vB.y*w1.y + vB.z*w1.z + vB.w*w1.w;
            a2B += vB.x*w2.x + vB.y*w2.y + vB.z*w2.z + vB.w*w2.w;
            a3B += vB.x*w3.x + vB.y*w3.y + vB.z*w3.z + vB.w*w3.w;
        }
        #pragma unroll
        for (int d = 1; d <= 2; d <<= 1){
            a0A += __shfl_xor_sync(0xffffffffu, a0A, d);
            a1A += __shfl_xor_sync(0xffffffffu, a1A, d);
            a2A += __shfl_xor_sync(0xffffffffu, a2A, d);
            a3A += __shfl_xor_sync(0xffffffffu, a3A, d);
            a0B += __shfl_xor_sync(0xffffffffu, a0B, d);
            a1B += __shfl_xor_sync(0xffffffffu, a1B, d);
            a2B += __shfl_xor_sync(0xffffffffu, a2B, d);
            a3B += __shfl_xor_sync(0xffffffffu, a3B, d);
        }
    }

    float hcA[4], hsA[4], hcB[4], hsB[4];
    {
        float xwA[4] = { a0A + sPB[0], a1A + sPB[1], a2A + sPB[2], a3A + sPB[3] };
        float xwB[4] = { a0B + sPB[0], a1B + sPB[1], a2B + sPB[2], a3B + sPB[3] };
        #pragma unroll
        for (int w = 0; w < 4; w++){
            __sincosf(0.5f * xwA[w], &hsA[w], &hcA[w]);
            __sincosf(0.5f * xwB[w], &hsB[w], &hcB[w]);
        }
    }

    // product-state magnitudes ((-1) of (-i)^popc folded in; (-i) itself is in U)
    float mA[16], mB[16];
    #pragma unroll
    for (int i = 0; i < 16; i++){
        float vA = ((i&8)?hsA[0]:hcA[0]) * ((i&4)?hsA[1]:hcA[1]) * ((i&2)?hsA[2]:hcA[2]) * ((i&1)?hsA[3]:hcA[3]);
        float vB = ((i&8)?hsB[0]:hcB[0]) * ((i&4)?hsB[1]:hcB[1]) * ((i&2)?hsB[2]:hcB[2]) * ((i&1)?hsB[3]:hcB[3]);
        if (__popc(i) & 2){ vA = -vA; vB = -vB; }
        mA[i] = vA; mB[i] = vB;
    }

    // ---- matvecs: shared U loads serve both samples ----
    unsigned long long pqA[4], pvA[4], pqB[4], pvB[4];
    #pragma unroll
    for (int r = 0; r < 4; r++){ pqA[r]=0ull; pvA[r]=0ull; pqB[r]=0ull; pvB[r]=0ull; }
    #pragma unroll
    for (int j = 0; j < 16; j++){
        unsigned long long mjA = pk2(mA[j], mA[j]);
        unsigned long long mjB = pk2(mB[j], mB[j]);
        ulonglong2 qa = Uq64[j*8 + 2*l];
        ulonglong2 qb = Uq64[j*8 + 2*l + 1];
        ulonglong2 va = Uv64[j*8 + 2*l];
        ulonglong2 vb = Uv64[j*8 + 2*l + 1];
        pqA[0] = fma2(qa.x, mjA, pqA[0]);  pqB[0] = fma2(qa.x, mjB, pqB[0]);
        pqA[1] = fma2(qa.y, mjA, pqA[1]);  pqB[1] = fma2(qa.y, mjB, pqB[1]);
        pqA[2] = fma2(qb.x, mjA, pqA[2]);  pqB[2] = fma2(qb.x, mjB, pqB[2]);
        pqA[3] = fma2(qb.y, mjA, pqA[3]);  pqB[3] = fma2(qb.y, mjB, pqB[3]);
        pvA[0] = fma2(va.x, mjA, pvA[0]);  pvB[0] = fma2(va.x, mjB, pvB[0]);
        pvA[1] = fma2(va.y, mjA, pvA[1]);  pvB[1] = fma2(va.y, mjB, pvB[1]);
        pvA[2] = fma2(vb.x, mjA, pvA[2]);  pvB[2] = fma2(vb.x, mjB, pvB[2]);
        pvA[3] = fma2(vb.y, mjA, pvA[3]);  pvB[3] = fma2(vb.y, mjB, pvB[3]);
    }
    float2 stqA[4], stvA[4], stqB[4], stvB[4];
    #pragma unroll
    for (int r = 0; r < 4; r++){
        stqA[r] = upk2(pqA[r]); stvA[r] = upk2(pvA[r]);
        stqB[r] = upk2(pqB[r]); stvB[r] = upk2(pvB[r]);
    }

    // ---- q path: RX(x) layer (symmetric pair update), both samples ----
    #pragma unroll
    for (int w = 0; w < 2; w++){
        int d = 2 >> w;   // wire0: lane^2, wire1: lane^1
        float cA = hcA[w], sA_ = hsA[w], cB = hcB[w], sB_ = hsB[w];
        #pragma unroll
        for (int r = 0; r < 4; r++){
            float2 oA = shflx(stqA[r], d);
            float2 oB = shflx(stqB[r], d);
            stqA[r] = make_float2(cA*stqA[r].x + sA_*oA.y, cA*stqA[r].y - sA_*oA.x);
            stqB[r] = make_float2(cB*stqB[r].x + sB_*oB.y, cB*stqB[r].y - sB_*oB.x);
        }
    }
    {   // wire2 (bit1): rows r <-> r^2
        float c = hcA[2], s = hsA[2];
        float2 n0 = make_float2(c*stqA[0].x + s*stqA[2].y, c*stqA[0].y - s*stqA[2].x);
        float2 n2 = make_float2(c*stqA[2].x + s*stqA[0].y, c*stqA[2].y - s*stqA[0].x);
        float2 n1 = make_float2(c*stqA[1].x + s*stqA[3].y, c*stqA[1].y - s*stqA[3].x);
        float2 n3 = make_float2(c*stqA[3].x + s*stqA[1].y, c*stqA[3].y - s*stqA[1].x);
        stqA[0]=n0; stqA[1]=n1; stqA[2]=n2; stqA[3]=n3;
        c = hcB[2]; s = hsB[2];
        n0 = make_float2(c*stqB[0].x + s*stqB[2].y, c*stqB[0].y - s*stqB[2].x);
        n2 = make_float2(c*stqB[2].x + s*stqB[0].y, c*stqB[2].y - s*stqB[0].x);
        n1 = make_float2(c*stqB[1].x + s*stqB[3].y, c*stqB[1].y - s*stqB[3].x);
        n3 = make_float2(c*stqB[3].x + s*stqB[1].y, c*stqB[3].y - s*stqB[1].x);
        stqB[0]=n0; stqB[1]=n1; stqB[2]=n2; stqB[3]=n3;
    }
    {   // wire3 (bit0): rows r <-> r^1
        float c = hcA[3], s = hsA[3];
        float2 n0 = make_float2(c*stqA[0].x + s*stqA[1].y, c*stqA[0].y - s*stqA[1].x);
        float2 n1 = make_float2(c*stqA[1].x + s*stqA[0].y, c*stqA[1].y - s*stqA[0].x);
        float2 n2 = make_float2(c*stqA[2].x + s*stqA[3].y, c*stqA[2].y - s*stqA[3].x);
        float2 n3 = make_float2(c*stqA[3].x + s*stqA[2].y, c*stqA[3].y - s*stqA[2].x);
        stqA[0]=n0; stqA[1]=n1; stqA[2]=n2; stqA[3]=n3;
        c = hcB[3]; s = hsB[3];
        n0 = make_float2(c*stqB[0].x + s*stqB[1].y, c*stqB[0].y - s*stqB[1].x);
        n1 = make_float2(c*stqB[1].x + s*stqB[0].y, c*stqB[1].y - s*stqB[0].x);
        n2 = make_float2(c*stqB[2].x + s*stqB[3].y, c*stqB[2].y - s*stqB[3].x);
        n3 = make_float2(c*stqB[3].x + s*stqB[2].y, c*stqB[3].y - s*stqB[2].x);
        stqB[0]=n0; stqB[1]=n1; stqB[2]=n2; stqB[3]=n3;
    }

    // ---- scores (both samples) ----
    float rzA[4], rzB[4];
    {
        float n0 = stqA[0].x*stqA[0].x + stqA[0].y*stqA[0].y;
        float n1 = stqA[1].x*stqA[1].x + stqA[1].y*stqA[1].y;
        float n2 = stqA[2].x*stqA[2].x + stqA[2].y*stqA[2].y;
        float n3 = stqA[3].x*stqA[3].x + stqA[3].y*stqA[3].y;
        float nsum = n0 + n1 + n2 + n3;
        float z0A = (l & 2) ? -nsum : nsum;
        float z1A = (l & 1) ? -nsum : nsum;
        float z2A = n0 + n1 - n2 - n3;
        float z3A = n0 - n1 + n2 - n3;

        n0 = stqB[0].x*stqB[0].x + stqB[0].y*stqB[0].y;
        n1 = stqB[1].x*stqB[1].x + stqB[1].y*stqB[1].y;
        n2 = stqB[2].x*stqB[2].x + stqB[2].y*stqB[2].y;
        n3 = stqB[3].x*stqB[3].x + stqB[3].y*stqB[3].y;
        nsum = n0 + n1 + n2 + n3;
        float z0B = (l & 2) ? -nsum : nsum;
        float z1B = (l & 1) ? -nsum : nsum;
        float z2B = n0 + n1 - n2 - n3;
        float z3B = n0 - n1 + n2 - n3;

        float x0A = 0.f, x1A = 0.f, x0B = 0.f, x1B = 0.f;
        #pragma unroll
        for (int r = 0; r < 4; r++){
            float2 oA = shflx(stqA[r], 2);
            float2 oB = shflx(stqB[r], 2);
            x0A += stqA[r].x*oA.x + stqA[r].y*oA.y;
            x0B += stqB[r].x*oB.x + stqB[r].y*oB.y;
        }
        #pragma unroll
        for (int r = 0; r < 4; r++){
            float2 oA = shflx(stqA[r], 1);
            float2 oB = shflx(stqB[r], 1);
            x1A += stqA[r].x*oA.x + stqA[r].y*oA.y;
            x1B += stqB[r].x*oB.x + stqB[r].y*oB.y;
        }
        float x2A = 2.f*(stqA[0].x*stqA[2].x + stqA[0].y*stqA[2].y + stqA[1].x*stqA[3].x + stqA[1].y*stqA[3].y);
        float x3A = 2.f*(stqA[0].x*stqA[1].x + stqA[0].y*stqA[1].y + stqA[2].x*stqA[3].x + stqA[2].y*stqA[3].y);
        float x2B = 2.f*(stqB[0].x*stqB[2].x + stqB[0].y*stqB[2].y + stqB[1].x*stqB[3].x + stqB[1].y*stqB[3].y);
        float x3B = 2.f*(stqB[0].x*stqB[1].x + stqB[0].y*stqB[1].y + stqB[2].x*stqB[3].x + stqB[2].y*stqB[3].y);

        #pragma unroll
        for (int d = 1; d <= 2; d <<= 1){
            z0A += __shfl_xor_sync(0xffffffffu, z0A, d);
            z1A += __shfl_xor_sync(0xffffffffu, z1A, d);
            z2A += __shfl_xor_sync(0xffffffffu, z2A, d);
            z3A += __shfl_xor_sync(0xffffffffu, z3A, d);
            x0A += __shfl_xor_sync(0xffffffffu, x0A, d);
            x1A += __shfl_xor_sync(0xffffffffu, x1A, d);
            x2A += __shfl_xor_sync(0xffffffffu, x2A, d);
            x3A += __shfl_xor_sync(0xffffffffu, x3A, d);
            z0B += __shfl_xor_sync(0xffffffffu, z0B, d);
            z1B += __shfl_xor_sync(0xffffffffu, z1B, d);
            z2B += __shfl_xor_sync(0xffffffffu, z2B, d);
            z3B += __shfl_xor_sync(0xffffffffu, z3B, d);
            x0B += __shfl_xor_sync(0xffffffffu, x0B, d);
            x1B += __shfl_xor_sync(0xffffffffu, x1B, d);
            x2B += __shfl_xor_sync(0xffffffffu, x2B, d);
            x3B += __shfl_xor_sync(0xffffffffu, x3B, d);
        }
        x0A *= sKx[0]; x1A *= sKx[1]; x2A *= sKx[2]; x3A *= sKx[3];
        x0B *= sKx[0]; x1B *= sKx[1]; x2B *= sKx[2]; x3B *= sKx[3];

        rzA[0] = fast_tanh(sqrtf(z0A*z0A + x0A*x0A)) * (0.5f * PI_F);
        rzA[1] = fast_tanh(sqrtf(z1A*z1A + x1A*x1A)) * (0.5f * PI_F);
        rzA[2] = fast_tanh(sqrtf(z2A*z2A + x2A*x2A)) * (0.5f * PI_F);
        rzA[3] = fast_tanh(sqrtf(z3A*z3A + x3A*x3A)) * (0.5f * PI_F);
        rzB[0] = fast_tanh(sqrtf(z0B*z0B + x0B*x0B)) * (0.5f * PI_F);
        rzB[1] = fast_tanh(sqrtf(z1B*z1B + x1B*x1B)) * (0.5f * PI_F);
        rzB[2] = fast_tanh(sqrtf(z2B*z2B + x2B*x2B)) * (0.5f * PI_F);
        rzB[3] = fast_tanh(sqrtf(z3B*z3B + x3B*x3B)) * (0.5f * PI_F);
    }

    // ---- v path: RZ phases ----
    {
        float phlA = ((l & 2) ? rzA[0] : -rzA[0]) + ((l & 1) ? rzA[1] : -rzA[1]);
        float phlB = ((l & 2) ? rzB[0] : -rzB[0]) + ((l & 1) ? rzB[1] : -rzB[1]);
        #pragma unroll
        for (int r = 0; r < 4; r++){
            float phA = phlA + ((r & 2) ? rzA[2] : -rzA[2]) + ((r & 1) ? rzA[3] : -rzA[3]);
            float phB = phlB + ((r & 2) ? rzB[2] : -rzB[2]) + ((r & 1) ? rzB[3] : -rzB[3]);
            float spA, cpA, spB, cpB;
            __sincosf(phA, &spA, &cpA);
            __sincosf(phB, &spB, &cpB);
            stvA[r] = make_float2(stvA[r].x*cpA - stvA[r].y*spA, stvA[r].x*spA + stvA[r].y*cpA);
            stvB[r] = make_float2(stvB[r].x*cpB - stvB[r].y*spB, stvB[r].x*spB + stvB[r].y*cpB);
        }
    }
    // CNOT(0,1): lanes with (l&2) take partner (l^1)'s value
    #pragma unroll
    for (int r = 0; r < 4; r++){
        float2 oA = shflx(stvA[r], 1);
        float2 oB = shflx(stvB[r], 1);
        if (l & 2){ stvA[r] = oA; stvB[r] = oB; }
    }
    // CNOT(1,2): if (l&1): swap rows r <-> r^2
    if (l & 1){
        float2 tq = stvA[0]; stvA[0] = stvA[2]; stvA[2] = tq;
        tq = stvA[1]; stvA[1] = stvA[3]; stvA[3] = tq;
        tq = stvB[0]; stvB[0] = stvB[2]; stvB[2] = tq;
        tq = stvB[1]; stvB[1] = stvB[3]; stvB[3] = tq;
    }
    // CNOT(2,3): swap rows 2,3
    { float2 tq = stvA[2]; stvA[2] = stvA[3]; stvA[3] = tq;
      tq = stvB[2]; stvB[2] = stvB[3]; stvB[3] = tq; }

    // ---- final expectations ----
    float o0A,o1A,o2A,o3A,o4A,o5A,o6A,o7A, o0B,o1B,o2B,o3B,o4B,o5B,o6B,o7B;
    {
        float n0 = stvA[0].x*stvA[0].x + stvA[0].y*stvA[0].y;
        float n1 = stvA[1].x*stvA[1].x + stvA[1].y*stvA[1].y;
        float n2 = stvA[2].x*stvA[2].x + stvA[2].y*stvA[2].y;
        float n3 = stvA[3].x*stvA[3].x + stvA[3].y*stvA[3].y;
        float qs = n0 + n1 + n2 + n3;
        o0A = (l & 2) ? -qs : qs;
        o1A = (l & 1) ? -qs : qs;
        o2A = n0 + n1 - n2 - n3;
        o3A = n0 - n1 + n2 - n3;

        n0 = stvB[0].x*stvB[0].x + stvB[0].y*stvB[0].y;
        n1 = stvB[1].x*stvB[1].x + stvB[1].y*stvB[1].y;
        n2 = stvB[2].x*stvB[2].x + stvB[2].y*stvB[2].y;
        n3 = stvB[3].x*stvB[3].x + stvB[3].y*stvB[3].y;
        qs = n0 + n1 + n2 + n3;
        o0B = (l & 2) ? -qs : qs;
        o1B = (l & 1) ? -qs : qs;
        o2B = n0 + n1 - n2 - n3;
        o3B = n0 - n1 + n2 - n3;

        o4A = 0.f; o5A = 0.f; o4B = 0.f; o5B = 0.f;
        #pragma unroll
        for (int r = 0; r < 4; r++){
            float2 oA = shflx(stvA[r], 2);
            float2 oB = shflx(stvB[r], 2);
            o4A += stvA[r].x*oA.x + stvA[r].y*oA.y;
            o4B += stvB[r].x*oB.x + stvB[r].y*oB.y;
        }
        #pragma unroll
        for (int r = 0; r < 4; r++){
            float2 oA = shflx(stvA[r], 1);
            float2 oB = shflx(stvB[r], 1);
            o5A += stvA[r].x*oA.x + stvA[r].y*oA.y;
            o5B += stvB[r].x*oB.x + stvB[r].y*oB.y;
        }
        o6A = 2.f*(stvA[0].x*stvA[2].x + stvA[0].y*stvA[2].y + stvA[1].x*stvA[3].x + stvA[1].y*stvA[3].y);
        o7A = 2.f*(stvA[0].x*stvA[1].x + stvA[0].y*stvA[1].y + stvA[2].x*stvA[3].x + stvA[2].y*stvA[3].y);
        o6B = 2.f*(stvB[0].x*stvB[2].x + stvB[0].y*stvB[2].y + stvB[1].x*stvB[3].x + stvB[1].y*stvB[3].y);
        o7B = 2.f*(stvB[0].x*stvB[1].x + stvB[0].y*stvB[1].y + stvB[2].x*stvB[3].x + stvB[2].y*stvB[3].y);

        #pragma unroll
        for (int d = 1; d <= 2; d <<= 1){
            o0A += __shfl_xor_sync(0xffffffffu, o0A, d);
            o1A += __shfl_xor_sync(0xffffffffu, o1A, d);
            o2A += __shfl_xor_sync(0xffffffffu, o2A, d);
            o3A += __shfl_xor_sync(0xffffffffu, o3A, d);
            o4A += __shfl_xor_sync(0xffffffffu, o4A, d);
            o5A += __shfl_xor_sync(0xffffffffu, o5A, d);
            o6A += __shfl_xor_sync(0xffffffffu, o6A, d);
            o7A += __shfl_xor_sync(0xffffffffu, o7A, d);
            o0B += __shfl_xor_sync(0xffffffffu, o0B, d);
            o1B += __shfl_xor_sync(0xffffffffu, o1B, d);
            o2B += __shfl_xor_sync(0xffffffffu, o2B, d);
            o3B += __shfl_xor_sync(0xffffffffu, o3B, d);
            o4B += __shfl_xor_sync(0xffffffffu, o4B, d);
            o5B += __shfl_xor_sync(0xffffffffu, o5B, d);
            o6B += __shfl_xor_sync(0xffffffffu, o6B, d);
            o7B += __shfl_xor_sync(0xffffffffu, o7B, d);
        }
    }

    if (l == 0){
        float oA[8] = { o0A,o1A,o2A,o3A,o4A,o5A,o6A,o7A };
        float oB[8] = { o0B,o1B,o2B,o3B,o4B,o5B,o6B,o7B };
        #pragma unroll
        for (int pass = 0; pass < 2; pass++){
            float* o = pass ? oB : oA;
            bool ok  = pass ? okB : okA;
            int  s   = pass ? sB  : sA;
            if (!ok) continue;
            float mu = 0.f;
            #pragma unroll
            for (int k = 0; k < 8; k++) mu += o[k];
            mu *= 0.125f;
            float var = 0.f;
            #pragma unroll
            for (int k = 0; k < 8; k++){ float dd = o[k] - mu; var += dd * dd; }
            var *= 0.125f;
            float inv = rsqrtf(var + 1e-5f);
            float r0 = sHB[0], r1 = sHB[1];
            #pragma unroll
            for (int k = 0; k < 8; k++){
                float y = (o[k] - mu) * inv * sLnW[k] + sLnB[k];
                float g = 0.5f * y * (1.f + erff(y * 0.70710678118654752f));
                r0 += g * sHW[k];
                r1 += g * sHW[8 + k];
            }
            ((float2*)out)[s] = make_float2(r0, r1);
        }
    }
}

extern "C" void kernel_launch(void* const* d_in, const int* in_sizes, int n_in,
                              void* d_out, int out_size)
{
    const float* x1     = (const float*)d_in[0];
    const float* pre_w  = (const float*)d_in[1];
    const float* pre_b  = (const float*)d_in[2];
    const float* q_rot  = (const float*)d_in[3];
    const float* k_rot  = (const float*)d_in[4];
    const float* v_rot  = (const float*)d_in[5];
    const float* q_crx  = (const float*)d_in[6];
    const float* k_crx  = (const float*)d_in[7];
    const float* v_crx  = (const float*)d_in[8];
    const float* ln_w   = (const float*)d_in[9];
    const float* ln_b   = (const float*)d_in[10];
    const float* head_w = (const float*)d_in[11];
    const float* head_b = (const float*)d_in[12];

    int B = in_sizes[0] / 96;

    qc_kernel<<<(B + 63) / 64, 128>>>(x1, pre_w, pre_b, q_rot, k_rot, v_rot,
                                      q_crx, k_crx, v_crx, ln_w, ln_b, head_w, head_b,
                                      (float*)d_out, B);
}

// round 11
// speedup vs baseline: 1.1794x; 1.1794x over previous
#include <cuda_runtime.h>
#include <math.h>

#define PI_F 3.14159265358979323846f

// Precomputed circuit data (setup_kernel -> qc_kernel)
// Odd-parity columns pre-rotated by (-i) so the matvec is a uniform f32x2 FMA.
__device__ float2 g_Uq[16][16];   // [col j][row i]
__device__ float2 g_Uv[16][16];
__device__ float  g_kx[4];        // <X_w> of the fixed k-register state

// ---------- helpers ----------
__device__ __forceinline__ float2 cmul(float2 a, float2 b){
    return make_float2(a.x*b.x - a.y*b.y, a.x*b.y + a.y*b.x);
}
__device__ __forceinline__ float2 cadd(float2 a, float2 b){ return make_float2(a.x+b.x, a.y+b.y); }
__device__ __forceinline__ float2 expi(float a){ float s,c; __sincosf(a,&s,&c); return make_float2(c,s); }
__device__ __forceinline__ float2 cscale(float2 a, float s){ return make_float2(a.x*s, a.y*s); }
__device__ __forceinline__ float2 shflx(float2 v, int m){
    return make_float2(__shfl_xor_sync(0xffffffffu, v.x, m),
                       __shfl_xor_sync(0xffffffffu, v.y, m));
}
__device__ __forceinline__ float fast_tanh(float x){
    float e = __expf(2.f * x);
    return 1.f - 2.f / (e + 1.f);
}
__device__ __forceinline__ unsigned long long pk2(float x, float y){
    unsigned long long r; asm("mov.b64 %0, {%1,%2};" : "=l"(r) : "f"(x), "f"(y)); return r;
}
__device__ __forceinline__ float2 upk2(unsigned long long a){
    float2 r; asm("mov.b64 {%0,%1}, %2;" : "=f"(r.x), "=f"(r.y) : "l"(a)); return r;
}
__device__ __forceinline__ unsigned long long fma2(unsigned long long a, unsigned long long b,
                                                   unsigned long long c){
    unsigned long long d;
    asm("fma.rn.f32x2 %0, %1, %2, %3;" : "=l"(d) : "l"(a), "l"(b), "l"(c));
    return d;
}

// fully-unrolled 8-gate initQKV circuit on 16 amplitudes across a 16-lane group
__device__ __forceinline__ float2 sim16(const float* __restrict__ rot,
                                        const float* __restrict__ crx,
                                        int col, int lane)
{
    float2 s = (lane == col) ? make_float2(1.f, 0.f) : make_float2(0.f, 0.f);
    #pragma unroll
    for (int g = 0; g < 8; g++){
        const int pa_[8] = {0,1,2,3,0,1,2,3};
        const int pb_[8] = {1,2,3,0,3,0,1,2};
        const int ma = 8 >> pa_[g], mb = 8 >> pb_[g];

        float phi = rot[3*g], th = rot[3*g+1], om = rot[3*g+2];
        float c, sn; __sincosf(0.5f*th, &sn, &c);
        float2 u00 = cscale(expi(-0.5f*(phi+om)),  c);
        float2 u01 = cscale(expi( 0.5f*(phi-om)), -sn);
        float2 u10 = cscale(expi(-0.5f*(phi-om)),  sn);
        float2 u11 = cscale(expi( 0.5f*(phi+om)),  c);
        float2 o = shflx(s, ma);
        s = (lane & ma) ? cadd(cmul(u10, o), cmul(u11, s))
                        : cadd(cmul(u00, s), cmul(u01, o));

        float cc, ss; __sincosf(0.5f*crx[g], &ss, &cc);
        o = shflx(s, mb);
        if (lane & ma) s = make_float2(cc*s.x + ss*o.y, cc*s.y - ss*o.x);

        o = shflx(s, mb);
        if (lane & ma) s = o;
    }
    return s;
}

// 17 blocks x 32 threads: block b handles chains 2b, 2b+1.
__global__ void __launch_bounds__(32)
setup_kernel(const float* __restrict__ qr, const float* __restrict__ kr,
             const float* __restrict__ vr, const float* __restrict__ qc,
             const float* __restrict__ kc, const float* __restrict__ vc)
{
    int grp  = blockIdx.x * 2 + (threadIdx.x >> 4);   // 0..33
    int lane = threadIdx.x & 15;

    const float* rot; const float* crx; int col;
    if (grp < 16)      { rot = qr; crx = qc; col = grp;      }
    else if (grp < 32) { rot = vr; crx = vc; col = grp - 16; }
    else               { rot = kr; crx = kc; col = 0;        }

    float2 s = sim16(rot, crx, col, lane);

    if (grp < 32){
        if (__popc(col) & 1) s = make_float2(s.y, -s.x);   // pre-rotate by (-i)
        if (grp < 16) g_Uq[col][lane] = s;
        else          g_Uv[col][lane] = s;
    } else {
        #pragma unroll
        for (int w = 0; w < 4; w++){
            int m = 8 >> w;
            float2 o = shflx(s, m);
            float v = s.x*o.x + s.y*o.y;
            v += __shfl_xor_sync(0xffffffffu, v, 1);
            v += __shfl_xor_sync(0xffffffffu, v, 2);
            v += __shfl_xor_sync(0xffffffffu, v, 4);
            v += __shfl_xor_sync(0xffffffffu, v, 8);
            if (grp == 32 && lane == 0) g_kx[w] = v;
        }
    }
}

// 128 threads = 32 quads; each quad serves TWO samples (ILP-2). 64 samples/block.
// Launched with PDL (programmatic stream serialization): the prologue up to the
// griddepcontrol.wait runs concurrently with setup_kernel.
__global__ void __launch_bounds__(128, 3)
qc_kernel(const float* __restrict__ x1, const float* __restrict__ pre_w,
          const float* __restrict__ pre_b,
          const float* __restrict__ ln_w, const float* __restrict__ ln_b,
          const float* __restrict__ head_w, const float* __restrict__ head_b,
          float* __restrict__ out, int B)
{
    __shared__ float4 sUq[128];   // 16x16 complex
    __shared__ float4 sUv[128];
    __shared__ float  sW[384];    // pre_w [4][96]
    __shared__ float  sKx[4];
    __shared__ float  sPB[4];
    __shared__ float  sLnW[8], sLnB[8], sHW[16], sHB[2];

    int t = threadIdx.x;

    // ---- phase 1: stage params that do NOT depend on setup_kernel ----
    for (int i = t; i < 384; i += 128) sW[i] = pre_w[i];
    if (t < 4)              sPB[t]     = pre_b[t];
    if (t >= 4 && t < 12)   sLnW[t-4]  = ln_w[t-4];
    if (t >= 12 && t < 20)  sLnB[t-12] = ln_b[t-12];
    if (t >= 20 && t < 36)  sHW[t-20]  = head_w[t-20];
    if (t >= 36 && t < 38)  sHB[t-36]  = head_b[t-36];
    __syncthreads();

    int q = t >> 2;                      // quad id 0..31
    int l = t & 3;                       // quad lane: rows 4l..4l+3
    int sA = blockIdx.x * 64 + q;
    int sB = sA + 32;
    bool okA = sA < B, okB = sB < B;
    int sAl = okA ? sA : 0;
    int sBl = okB ? sB : 0;

    const float4* sW4 = (const float4*)sW;

    // ---- x = x1[s] @ pre_w.T + pre_b, both samples (setup-independent) ----
    float a0A=0.f,a1A=0.f,a2A=0.f,a3A=0.f, a0B=0.f,a1B=0.f,a2B=0.f,a3B=0.f;
    {
        const float4* rowA = (const float4*)(x1 + (size_t)sAl * 96) + l * 6;
        const float4* rowB = (const float4*)(x1 + (size_t)sBl * 96) + l * 6;
        #pragma unroll
        for (int k = 0; k < 6; k++){
            float4 vA = rowA[k];
            float4 vB = rowB[k];
            float4 w0 = sW4[      l*6 + k];
            float4 w1 = sW4[ 24 + l*6 + k];
            float4 w2 = sW4[ 48 + l*6 + k];
            float4 w3 = sW4[ 72 + l*6 + k];
            a0A += vA.x*w0.x + vA.y*w0.y + vA.z*w0.z + vA.w*w0.w;
            a1A += vA.x*w1.x + vA.y*w1.y + vA.z*w1.z + vA.w*w1.w;
            a2A += vA.x*w2.x + vA.y*w2.y + vA.z*w2.z + vA.w*w2.w;
            a3A += vA.x*w3.x + vA.y*w3.y + vA.z*w3.z + vA.w*w3.w;
            a0B += vB.x*w0.x + vB.y*w0.y + vB.z*w0.z + vB.w*w0.w;
            a1B += vB.x*w1.x + vB.y*w1.y + vB.z*w1.z + vB.w*w1.w;
            a2B += vB.x*w2.x + vB.y*w2.y + vB.z*w2.z + vB.w*w2.w;
            a3B += vB.x*w3.x + vB.y*w3.y + vB.z*w3.z + vB.w*w3.w;
        }
        #pragma unroll
        for (int d = 1; d <= 2; d <<= 1){
            a0A += __shfl_xor_sync(0xffffffffu, a0A, d);
            a1A += __shfl_xor_sync(0xffffffffu, a1A, d);
            a2A += __shfl_xor_sync(0xffffffffu, a2A, d);
            a3A += __shfl_xor_sync(0xffffffffu, a3A, d);
            a0B += __shfl_xor_sync(0xffffffffu, a0B, d);
            a1B += __shfl_xor_sync(0xffffffffu, a1B, d);
            a2B += __shfl_xor_sync(0xffffffffu, a2B, d);
            a3B += __shfl_xor_sync(0xffffffffu, a3B, d);
        }
    }

    float hcA[4], hsA[4], hcB[4], hsB[4];
    {
        float xwA[4] = { a0A + sPB[0], a1A + sPB[1], a2A + sPB[2], a3A + sPB[3] };
        float xwB[4] = { a0B + sPB[0], a1B + sPB[1], a2B + sPB[2], a3B + sPB[3] };
        #pragma unroll
        for (int w = 0; w < 4; w++){
            __sincosf(0.5f * xwA[w], &hsA[w], &hcA[w]);
            __sincosf(0.5f * xwB[w], &hsB[w], &hcB[w]);
        }
    }

    // product-state magnitudes ((-1) of (-i)^popc folded in; (-i) itself is in U)
    float mA[16], mB[16];
    #pragma unroll
    for (int i = 0; i < 16; i++){
        float vA = ((i&8)?hsA[0]:hcA[0]) * ((i&4)?hsA[1]:hcA[1]) * ((i&2)?hsA[2]:hcA[2]) * ((i&1)?hsA[3]:hcA[3]);
        float vB = ((i&8)?hsB[0]:hcB[0]) * ((i&4)?hsB[1]:hcB[1]) * ((i&2)?hsB[2]:hcB[2]) * ((i&1)?hsB[3]:hcB[3]);
        if (__popc(i) & 2){ vA = -vA; vB = -vB; }
        mA[i] = vA; mB[i] = vB;
    }

    // ---- phase 2: wait for setup_kernel's results, then stage them ----
    asm volatile("griddepcontrol.wait;" ::: "memory");
    sUq[t] = ((const float4*)g_Uq)[t];
    sUv[t] = ((const float4*)g_Uv)[t];
    if (t < 4) sKx[t] = g_kx[t];
    __syncthreads();

    const ulonglong2* Uq64 = (const ulonglong2*)sUq;
    const ulonglong2* Uv64 = (const ulonglong2*)sUv;

    // ---- matvecs: shared U loads serve both samples ----
    unsigned long long pqA[4], pvA[4], pqB[4], pvB[4];
    #pragma unroll
    for (int r = 0; r < 4; r++){ pqA[r]=0ull; pvA[r]=0ull; pqB[r]=0ull; pvB[r]=0ull; }
    #pragma unroll
    for (int j = 0; j < 16; j++){
        unsigned long long mjA = pk2(mA[j], mA[j]);
        unsigned long long mjB = pk2(mB[j], mB[j]);
        ulonglong2 qa = Uq64[j*8 + 2*l];
        ulonglong2 qb = Uq64[j*8 + 2*l + 1];
        ulonglong2 va = Uv64[j*8 + 2*l];
        ulonglong2 vb = Uv64[j*8 + 2*l + 1];
        pqA[0] = fma2(qa.x, mjA, pqA[0]);  pqB[0] = fma2(qa.x, mjB, pqB[0]);
        pqA[1] = fma2(qa.y, mjA, pqA[1]);  pqB[1] = fma2(qa.y, mjB, pqB[1]);
        pqA[2] = fma2(qb.x, mjA, pqA[2]);  pqB[2] = fma2(qb.x, mjB, pqB[2]);
        pqA[3] = fma2(qb.y, mjA, pqA[3]);  pqB[3] = fma2(qb.y, mjB, pqB[3]);
        pvA[0] = fma2(va.x, mjA, pvA[0]);  pvB[0] = fma2(va.x, mjB, pvB[0]);
        pvA[1] = fma2(va.y, mjA, pvA[1]);  pvB[1] = fma2(va.y, mjB, pvB[1]);
        pvA[2] = fma2(vb.x, mjA, pvA[2]);  pvB[2] = fma2(vb.x, mjB, pvB[2]);
        pvA[3] = fma2(vb.y, mjA, pvA[3]);  pvB[3] = fma2(vb.y, mjB, pvB[3]);
    }
    float2 stqA[4], stvA[4], stqB[4], stvB[4];
    #pragma unroll
    for (int r = 0; r < 4; r++){
        stqA[r] = upk2(pqA[r]); stvA[r] = upk2(pvA[r]);
        stqB[r] = upk2(pqB[r]); stvB[r] = upk2(pvB[r]);
    }

    // ---- q path: RX(x) layer (symmetric pair update), both samples ----
    #pragma unroll
    for (int w = 0; w < 2; w++){
        int d = 2 >> w;   // wire0: lane^2, wire1: lane^1
        float cA = hcA[w], sA_ = hsA[w], cB = hcB[w], sB_ = hsB[w];
        #pragma unroll
        for (int r = 0; r < 4; r++){
            float2 oA = shflx(stqA[r], d);
            float2 oB = shflx(stqB[r], d);
            stqA[r] = make_float2(cA*stqA[r].x + sA_*oA.y, cA*stqA[r].y - sA_*oA.x);
            stqB[r] = make_float2(cB*stqB[r].x + sB_*oB.y, cB*stqB[r].y - sB_*oB.x);
        }
    }
    {   // wire2 (bit1): rows r <-> r^2
        float c = hcA[2], s = hsA[2];
        float2 n0 = make_float2(c*stqA[0].x + s*stqA[2].y, c*stqA[0].y - s*stqA[2].x);
        float2 n2 = make_float2(c*stqA[2].x + s*stqA[0].y, c*stqA[2].y - s*stqA[0].x);
        float2 n1 = make_float2(c*stqA[1].x + s*stqA[3].y, c*stqA[1].y - s*stqA[3].x);
        float2 n3 = make_float2(c*stqA[3].x + s*stqA[1].y, c*stqA[3].y - s*stqA[1].x);
        stqA[0]=n0; stqA[1]=n1; stqA[2]=n2; stqA[3]=n3;
        c = hcB[2]; s = hsB[2];
        n0 = make_float2(c*stqB[0].x + s*stqB[2].y, c*stqB[0].y - s*stqB[2].x);
        n2 = make_float2(c*stqB[2].x + s*stqB[0].y, c*stqB[2].y - s*stqB[0].x);
        n1 = make_float2(c*stqB[1].x + s*stqB[3].y, c*stqB[1].y - s*stqB[3].x);
        n3 = make_float2(c*stqB[3].x + s*stqB[1].y, c*stqB[3].y - s*stqB[1].x);
        stqB[0]=n0; stqB[1]=n1; stqB[2]=n2; stqB[3]=n3;
    }
    {   // wire3 (bit0): rows r <-> r^1
        float c = hcA[3], s = hsA[3];
        float2 n0 = make_float2(c*stqA[0].x + s*stqA[1].y, c*stqA[0].y - s*stqA[1].x);
        float2 n1 = make_float2(c*stqA[1].x + s*stqA[0].y, c*stqA[1].y - s*stqA[0].x);
        float2 n2 = make_float2(c*stqA[2].x + s*stqA[3].y, c*stqA[2].y - s*stqA[3].x);
        float2 n3 = make_float2(c*stqA[3].x + s*stqA[2].y, c*stqA[3].y - s*stqA[2].x);
        stqA[0]=n0; stqA[1]=n1; stqA[2]=n2; stqA[3]=n3;
        c = hcB[3]; s = hsB[3];
        n0 = make_float2(c*stqB[0].x + s*stqB[1].y, c*stqB[0].y - s*stqB[1].x);
        n1 = make_float2(c*stqB[1].x + s*stqB[0].y, c*stqB[1].y - s*stqB[0].x);
        n2 = make_float2(c*stqB[2].x + s*stqB[3].y, c*stqB[2].y - s*stqB[3].x);
        n3 = make_float2(c*stqB[3].x + s*stqB[2].y, c*stqB[3].y - s*stqB[2].x);
        stqB[0]=n0; stqB[1]=n1; stqB[2]=n2; stqB[3]=n3;
    }

    // ---- scores (both samples) ----
    float rzA[4], rzB[4];
    {
        float n0 = stqA[0].x*stqA[0].x + stqA[0].y*stqA[0].y;
        float n1 = stqA[1].x*stqA[1].x + stqA[1].y*stqA[1].y;
        float n2 = stqA[2].x*stqA[2].x + stqA[2].y*stqA[2].y;
        float n3 = stqA[3].x*stqA[3].x + stqA[3].y*stqA[3].y;
        float nsum = n0 + n1 + n2 + n3;
        float z0A = (l & 2) ? -nsum : nsum;
        float z1A = (l & 1) ? -nsum : nsum;
        float z2A = n0 + n1 - n2 - n3;
        float z3A = n0 - n1 + n2 - n3;

        n0 = stqB[0].x*stqB[0].x + stqB[0].y*stqB[0].y;
        n1 = stqB[1].x*stqB[1].x + stqB[1].y*stqB[1].y;
        n2 = stqB[2].x*stqB[2].x + stqB[2].y*stqB[2].y;
        n3 = stqB[3].x*stqB[3].x + stqB[3].y*stqB[3].y;
        nsum = n0 + n1 + n2 + n3;
        float z0B = (l & 2) ? -nsum : nsum;
        float z1B = (l & 1) ? -nsum : nsum;
        float z2B = n0 + n1 - n2 - n3;
        float z3B = n0 - n1 + n2 - n3;

        float x0A = 0.f, x1A = 0.f, x0B = 0.f, x1B = 0.f;
        #pragma unroll
        for (int r = 0; r < 4; r++){
            float2 oA = shflx(stqA[r], 2);
            float2 oB = shflx(stqB[r], 2);
            x0A += stqA[r].x*oA.x + stqA[r].y*oA.y;
            x0B += stqB[r].x*oB.x + stqB[r].y*oB.y;
        }
        #pragma unroll
        for (int r = 0; r < 4; r++){
            float2 oA = shflx(stqA[r], 1);
            float2 oB = shflx(stqB[r], 1);
            x1A += stqA[r].x*oA.x + stqA[r].y*oA.y;
            x1B += stqB[r].x*oB.x + stqB[r].y*oB.y;
        }
        float x2A = 2.f*(stqA[0].x*stqA[2].x + stqA[0].y*stqA[2].y + stqA[1].x*stqA[3].x + stqA[1].y*stqA[3].y);
        float x3A = 2.f*(stqA[0].x*stqA[1].x + stqA[0].y*stqA[1].y + stqA[2].x*stqA[3].x + stqA[2].y*stqA[3].y);
        float x2B = 2.f*(stqB[0].x*stqB[2].x + stqB[0].y*stqB[2].y + stqB[1].x*stqB[3].x + stqB[1].y*stqB[3].y);
        float x3B = 2.f*(stqB[0].x*stqB[1].x + stqB[0].y*stqB[1].y + stqB[2].x*stqB[3].x + stqB[2].y*stqB[3].y);

        #pragma unroll
        for (int d = 1; d <= 2; d <<= 1){
            z0A += __shfl_xor_sync(0xffffffffu, z0A, d);
            z1A += __shfl_xor_sync(0xffffffffu, z1A, d);
            z2A += __shfl_xor_sync(0xffffffffu, z2A, d);
            z3A += __shfl_xor_sync(0xffffffffu, z3A, d);
            x0A += __shfl_xor_sync(0xffffffffu, x0A, d);
            x1A += __shfl_xor_sync(0xffffffffu, x1A, d);
            x2A += __shfl_xor_sync(0xffffffffu, x2A, d);
            x3A += __shfl_xor_sync(0xffffffffu, x3A, d);
            z0B += __shfl_xor_sync(0xffffffffu, z0B, d);
            z1B += __shfl_xor_sync(0xffffffffu, z1B, d);
            z2B += __shfl_xor_sync(0xffffffffu, z2B, d);
            z3B += __shfl_xor_sync(0xffffffffu, z3B, d);
            x0B += __shfl_xor_sync(0xffffffffu, x0B, d);
            x1B += __shfl_xor_sync(0xffffffffu, x1B, d);
            x2B += __shfl_xor_sync(0xffffffffu, x2B, d);
            x3B += __shfl_xor_sync(0xffffffffu, x3B, d);
        }
        x0A *= sKx[0]; x1A *= sKx[1]; x2A *= sKx[2]; x3A *= sKx[3];
        x0B *= sKx[0]; x1B *= sKx[1]; x2B *= sKx[2]; x3B *= sKx[3];

        rzA[0] = fast_tanh(sqrtf(z0A*z0A + x0A*x0A)) * (0.5f * PI_F);
        rzA[1] = fast_tanh(sqrtf(z1A*z1A + x1A*x1A)) * (0.5f * PI_F);
        rzA[2] = fast_tanh(sqrtf(z2A*z2A + x2A*x2A)) * (0.5f * PI_F);
        rzA[3] = fast_tanh(sqrtf(z3A*z3A + x3A*x3A)) * (0.5f * PI_F);
        rzB[0] = fast_tanh(sqrtf(z0B*z0B + x0B*x0B)) * (0.5f * PI_F);
        rzB[1] = fast_tanh(sqrtf(z1B*z1B + x1B*x1B)) * (0.5f * PI_F);
        rzB[2] = fast_tanh(sqrtf(z2B*z2B + x2B*x2B)) * (0.5f * PI_F);
        rzB[3] = fast_tanh(sqrtf(z3B*z3B + x3B*x3B)) * (0.5f * PI_F);
    }

    // ---- v path: RZ phases ----
    {
        float phlA = ((l & 2) ? rzA[0] : -rzA[0]) + ((l & 1) ? rzA[1] : -rzA[1]);
        float phlB = ((l & 2) ? rzB[0] : -rzB[0]) + ((l & 1) ? rzB[1] : -rzB[1]);
        #pragma unroll
        for (int r = 0; r < 4; r++){
            float phA = phlA + ((r & 2) ? rzA[2] : -rzA[2]) + ((r & 1) ? rzA[3] : -rzA[3]);
            float phB = phlB + ((r & 2) ? rzB[2] : -rzB[2]) + ((r & 1) ? rzB[3] : -rzB[3]);
            float spA, cpA, spB, cpB;
            __sincosf(phA, &spA, &cpA);
            __sincosf(phB, &spB, &cpB);
            stvA[r] = make_float2(stvA[r].x*cpA - stvA[r].y*spA, stvA[r].x*spA + stvA[r].y*cpA);
            stvB[r] = make_float2(stvB[r].x*cpB - stvB[r].y*spB, stvB[r].x*spB + stvB[r].y*cpB);
        }
    }
    // CNOT(0,1): lanes with (l&2) take partner (l^1)'s value
    #pragma unroll
    for (int r = 0; r < 4; r++){
        float2 oA = shflx(stvA[r], 1);
        float2 oB = shflx(stvB[r], 1);
        if (l & 2){ stvA[r] = oA; stvB[r] = oB; }
    }
    // CNOT(1,2): if (l&1): swap rows r <-> r^2
    if (l & 1){
        float2 tq = stvA[0]; stvA[0] = stvA[2]; stvA[2] = tq;
        tq = stvA[1]; stvA[1] = stvA[3]; stvA[3] = tq;
        tq = stvB[0]; stvB[0] = stvB[2]; stvB[2] = tq;
        tq = stvB[1]; stvB[1] = stvB[3]; stvB[3] = tq;
    }
    // CNOT(2,3): swap rows 2,3
    { float2 tq = stvA[2]; stvA[2] = stvA[3]; stvA[3] = tq;
      tq = stvB[2]; stvB[2] = stvB[3]; stvB[3] = tq; }

    // ---- final expectations ----
    float o0A,o1A,o2A,o3A,o4A,o5A,o6A,o7A, o0B,o1B,o2B,o3B,o4B,o5B,o6B,o7B;
    {
        float n0 = stvA[0].x*stvA[0].x + stvA[0].y*stvA[0].y;
        float n1 = stvA[1].x*stvA[1].x + stvA[1].y*stvA[1].y;
        float n2 = stvA[2].x*stvA[2].x + stvA[2].y*stvA[2].y;
        float n3 = stvA[3].x*stvA[3].x + stvA[3].y*stvA[3].y;
        float qs = n0 + n1 + n2 + n3;
        o0A = (l & 2) ? -qs : qs;
        o1A = (l & 1) ? -qs : qs;
        o2A = n0 + n1 - n2 - n3;
        o3A = n0 - n1 + n2 - n3;

        n0 = stvB[0].x*stvB[0].x + stvB[0].y*stvB[0].y;
        n1 = stvB[1].x*stvB[1].x + stvB[1].y*stvB[1].y;
        n2 = stvB[2].x*stvB[2].x + stvB[2].y*stvB[2].y;
        n3 = stvB[3].x*stvB[3].x + stvB[3].y*stvB[3].y;
        qs = n0 + n1 + n2 + n3;
        o0B = (l & 2) ? -qs : qs;
        o1B = (l & 1) ? -qs : qs;
        o2B = n0 + n1 - n2 - n3;
        o3B = n0 - n1 + n2 - n3;

        o4A = 0.f; o5A = 0.f; o4B = 0.f; o5B = 0.f;
        #pragma unroll
        for (int r = 0; r < 4; r++){
            float2 oA = shflx(stvA[r], 2);
            float2 oB = shflx(stvB[r], 2);
            o4A += stvA[r].x*oA.x + stvA[r].y*oA.y;
            o4B += stvB[r].x*oB.x + stvB[r].y*oB.y;
        }
        #pragma unroll
        for (int r = 0; r < 4; r++){
            float2 oA = shflx(stvA[r], 1);
            float2 oB = shflx(stvB[r], 1);
            o5A += stvA[r].x*oA.x + stvA[r].y*oA.y;
            o5B += stvB[r].x*oB.x + stvB[r].y*oB.y;
        }
        o6A = 2.f*(stvA[0].x*stvA[2].x + stvA[0].y*stvA[2].y + stvA[1].x*stvA[3].x + stvA[1].y*stvA[3].y);
        o7A = 2.f*(stvA[0].x*stvA[1].x + stvA[0].y*stvA[1].y + stvA[2].x*stvA[3].x + stvA[2].y*stvA[3].y);
        o6B = 2.f*(stvB[0].x*stvB[2].x + stvB[0].y*stvB[2].y + stvB[1].x*stvB[3].x + stvB[1].y*stvB[3].y);
        o7B = 2.f*(stvB[0].x*stvB[1].x + stvB[0].y*stvB[1].y + stvB[2].x*stvB[3].x + stvB[2].y*stvB[3].y);

        #pragma unroll
        for (int d = 1; d <= 2; d <<= 1){
            o0A += __shfl_xor_sync(0xffffffffu, o0A, d);
            o1A += __shfl_xor_sync(0xffffffffu, o1A, d);
            o2A += __shfl_xor_sync(0xffffffffu, o2A, d);
            o3A += __shfl_xor_sync(0xffffffffu, o3A, d);
            o4A += __shfl_xor_sync(0xffffffffu, o4A, d);
            o5A += __shfl_xor_sync(0xffffffffu, o5A, d);
            o6A += __shfl_xor_sync(0xffffffffu, o6A, d);
            o7A += __shfl_xor_sync(0xffffffffu, o7A, d);
            o0B += __shfl_xor_sync(0xffffffffu, o0B, d);
            o1B += __shfl_xor_sync(0xffffffffu, o1B, d);
            o2B += __shfl_xor_sync(0xffffffffu, o2B, d);
            o3B += __shfl_xor_sync(0xffffffffu, o3B, d);
            o4B += __shfl_xor_sync(0xffffffffu, o4B, d);
            o5B += __shfl_xor_sync(0xffffffffu, o5B, d);
            o6B += __shfl_xor_sync(0xffffffffu, o6B, d);
            o7B += __shfl_xor_sync(0xffffffffu, o7B, d);
        }
    }

    // ---- distributed LN / GELU / head: lane l handles channels 2l, 2l+1 ----
    {
        int c0 = 2*l, c1 = 2*l + 1;
        float e0A = (l==0)?o0A:(l==1)?o2A:(l==2)?o4A:o6A;
        float e1A = (l==0)?o1A:(l==1)?o3A:(l==2)?o5A:o7A;
        float e0B = (l==0)?o0B:(l==1)?o2B:(l==2)?o4B:o6B;
        float e1B = (l==0)?o1B:(l==1)?o3B:(l==2)?o5B:o7B;

        float mpA = e0A + e1A, mpB = e0B + e1B;
        mpA += __shfl_xor_sync(0xffffffffu, mpA, 1);
        mpB += __shfl_xor_sync(0xffffffffu, mpB, 1);
        mpA += __shfl_xor_sync(0xffffffffu, mpA, 2);
        mpB += __shfl_xor_sync(0xffffffffu, mpB, 2);
        float muA = mpA * 0.125f, muB = mpB * 0.125f;

        float d0A = e0A - muA, d1A = e1A - muA;
        float d0B = e0B - muB, d1B = e1B - muB;
        float vpA = d0A*d0A + d1A*d1A;
        float vpB = d0B*d0B + d1B*d1B;
        vpA += __shfl_xor_sync(0xffffffffu, vpA, 1);
        vpB += __shfl_xor_sync(0xffffffffu, vpB, 1);
        vpA += __shfl_xor_sync(0xffffffffu, vpA, 2);
        vpB += __shfl_xor_sync(0xffffffffu, vpB, 2);
        float invA = rsqrtf(vpA * 0.125f + 1e-5f);
        float invB = rsqrtf(vpB * 0.125f + 1e-5f);

        float w0 = sLnW[c0], w1 = sLnW[c1], bb0 = sLnB[c0], bb1 = sLnB[c1];
        float y0A = d0A*invA*w0 + bb0, y1A = d1A*invA*w1 + bb1;
        float y0B = d0B*invB*w0 + bb0, y1B = d1B*invB*w1 + bb1;

        const float RS2 = 0.70710678118654752f;
        float g0A = 0.5f*y0A*(1.f + erff(y0A*RS2));
        float g1A = 0.5f*y1A*(1.f + erff(y1A*RS2));
        float g0B = 0.5f*y0B*(1.f + erff(y0B*RS2));
        float g1B = 0.5f*y1B*(1.f + erff(y1B*RS2));

        float hw00 = sHW[c0], hw01 = sHW[c1], hw10 = sHW[8+c0], hw11 = sHW[8+c1];
        float r0A = g0A*hw00 + g1A*hw01;
        float r1A = g0A*hw10 + g1A*hw11;
        float r0B = g0B*hw00 + g1B*hw01;
        float r1B = g0B*hw10 + g1B*hw11;
        r0A += __shfl_xor_sync(0xffffffffu, r0A, 1);
        r1A += __shfl_xor_sync(0xffffffffu, r1A, 1);
        r0B += __shfl_xor_sync(0xffffffffu, r0B, 1);
        r1B += __shfl_xor_sync(0xffffffffu, r1B, 1);
        r0A += __shfl_xor_sync(0xffffffffu, r0A, 2);
        r1A += __shfl_xor_sync(0xffffffffu, r1A, 2);
        r0B += __shfl_xor_sync(0xffffffffu, r0B, 2);
        r1B += __shfl_xor_sync(0xffffffffu, r1B, 2);

        if (l == 0){
            if (okA) ((float2*)out)[sA] = make_float2(r0A + sHB[0], r1A + sHB[1]);
            if (okB) ((float2*)out)[sB] = make_float2(r0B + sHB[0], r1B + sHB[1]);
        }
    }
}

extern "C" void kernel_launch(void* const* d_in, const int* in_sizes, int n_in,
                              void* d_out, int out_size)
{
    const float* x1     = (const float*)d_in[0];
    const float* pre_w  = (const float*)d_in[1];
    const float* pre_b  = (const float*)d_in[2];
    const float* q_rot  = (const float*)d_in[3];
    const float* k_rot  = (const float*)d_in[4];
    const float* v_rot  = (const float*)d_in[5];
    const float* q_crx  = (const float*)d_in[6];
    const float* k_crx  = (const float*)d_in[7];
    const float* v_crx  = (const float*)d_in[8];
    const float* ln_w   = (const float*)d_in[9];
    const float* ln_b   = (const float*)d_in[10];
    const float* head_w = (const float*)d_in[11];
    const float* head_b = (const float*)d_in[12];

    int B = in_sizes[0] / 96;

    setup_kernel<<<17, 32>>>(q_rot, k_rot, v_rot, q_crx, k_crx, v_crx);

    // PDL launch: qc's prologue overlaps setup_kernel; griddepcontrol.wait
    // inside qc orders the g_U* reads after setup completion.
    cudaLaunchConfig_t cfg = {};
    cfg.gridDim  = dim3((unsigned)((B + 63) / 64), 1, 1);
    cfg.blockDim = dim3(128, 1, 1);
    cfg.dynamicSmemBytes = 0;
    cfg.stream = 0;
    cudaLaunchAttribute attrs[1];
    attrs[0].id = cudaLaunchAttributeProgrammaticStreamSerialization;
    attrs[0].val.programmaticStreamSerializationAllowed = 1;
    cfg.attrs = attrs;
    cfg.numAttrs = 1;
    cudaLaunchKernelEx(&cfg, qc_kernel, x1, pre_w, pre_b, ln_w, ln_b,
                       head_w, head_b, (float*)d_out, B);
}